// round 1
// baseline (speedup 1.0000x reference)
#include <cuda_runtime.h>
#include <cuda_bf16.h>

#define NG   1024
#define IMG_W 256
#define IMG_H 256
#define QMAX 28.0f   // alpha cutoff: 0.1*exp(-14) ~ 8e-8 per gaussian

// Preprocessed gaussian params (SoA, float4 for LDS.128)
__device__ float4 g_pos[NG];   // mx, my, rx, ry   (bbox radii at q=QMAX)
__device__ float4 g_cov[NG];   // ia, ib, id, op   (inverse covariance + opacity)

__global__ void prep_kernel(const float* __restrict__ means,
                            const float* __restrict__ scales,
                            const float* __restrict__ thetas,
                            const float* __restrict__ opacities) {
    int i = blockIdx.x * blockDim.x + threadIdx.x;
    if (i >= NG) return;

    float mx = tanhf(means[2 * i + 0]);
    float my = tanhf(means[2 * i + 1]);
    float s0 = expf(scales[2 * i + 0]);
    float s1 = expf(scales[2 * i + 1]);
    float th = (2.0f * 3.14159265358979323846f) / (1.0f + expf(-thetas[i]));
    float op = 1.0f / (1.0f + expf(-opacities[i]));

    float si, c;
    sincosf(th, &si, &c);
    float s02 = s0 * s0, s12 = s1 * s1;
    const float J = 1e-6f;
    float a = c * c * s02 + si * si * s12 + J;   // Sigma_00
    float b = c * si * (s02 - s12);              // Sigma_01
    float d = si * si * s02 + c * c * s12 + J;   // Sigma_11
    float det = a * d - b * b;
    float inv = 1.0f / det;
    float ia  =  d * inv;
    float ib  = -b * inv;
    float idd =  a * inv;

    // bbox of {z : z^T Sigma^{-1} z <= QMAX}: |dx| <= sqrt(QMAX*Sigma_00)
    float rx = sqrtf(QMAX * a);
    float ry = sqrtf(QMAX * d);

    g_pos[i] = make_float4(mx, my, rx, ry);
    g_cov[i] = make_float4(ia, ib, idd, op);
}

__global__ void __launch_bounds__(256) render_kernel(float* __restrict__ out) {
    __shared__ float4 sp[NG];   // 16KB
    __shared__ float4 sc[NG];   // 16KB

    int tid = threadIdx.y * 16 + threadIdx.x;
    // Stage all gaussian params into smem (broadcast reads thereafter)
    #pragma unroll
    for (int i = tid; i < NG; i += 256) {
        sp[i] = g_pos[i];
        sc[i] = g_cov[i];
    }
    __syncthreads();

    int px = blockIdx.x * 16 + threadIdx.x;
    int py = blockIdx.y * 16 + threadIdx.y;
    float x = -1.0f + (float)px * (2.0f / 255.0f);
    float y = -1.0f + (float)py * (2.0f / 255.0f);

    float acc = 0.0f;
    float T = 1.0f;

    #pragma unroll 4
    for (int i = 0; i < NG; ++i) {
        float4 p = sp[i];
        float dx = x - p.x;
        float dy = y - p.y;
        // conservative bbox reject — warp-mostly-uniform
        if (fabsf(dx) < p.z && fabsf(dy) < p.w) {
            float4 cv = sc[i];
            float u = cv.x * dx + cv.y * dy;
            float v = cv.y * dx + cv.z * dy;
            float q = u * dx + v * dy;   // Mahalanobis dist^2
            if (q < QMAX) {
                float alpha = cv.w * __expf(-0.5f * q);
                acc += alpha * T;
                T *= (1.0f - alpha);
            }
        }
    }

    // BG_COLOR = 0 -> all three channels equal acc
    int o = (py * IMG_W + px) * 3;
    out[o + 0] = acc;
    out[o + 1] = acc;
    out[o + 2] = acc;
}

extern "C" void kernel_launch(void* const* d_in, const int* in_sizes, int n_in,
                              void* d_out, int out_size) {
    const float* means     = (const float*)d_in[0];
    const float* scales    = (const float*)d_in[1];
    const float* thetas    = (const float*)d_in[2];
    const float* opacities = (const float*)d_in[3];
    float* out = (float*)d_out;

    prep_kernel<<<4, 256>>>(means, scales, thetas, opacities);
    render_kernel<<<dim3(IMG_W / 16, IMG_H / 16), dim3(16, 16)>>>(out);
}

// round 2
// speedup vs baseline: 2.7111x; 2.7111x over previous
#include <cuda_runtime.h>
#include <cuda_bf16.h>

#define NG      1024
#define NCHUNK  4
#define CHUNK   (NG / NCHUNK)          // 256
#define IMG_W   256
#define IMG_H   256
#define NPIX    (IMG_W * IMG_H)
#define QMAX    18.0f                  // truncation err ~1.3e-4 rel (validated model)

// Preprocessed gaussian params (SoA)
__device__ float4 g_pos[NG];           // mx, my, rx, ry  (bbox radii at q=QMAX)
__device__ float4 g_cov[NG];           // ia, ib, id, op  (inverse covariance + opacity)
// Per-chunk partial composites: (acc, T) per pixel
__device__ float2 g_part[NCHUNK * NPIX];

__global__ void prep_kernel(const float* __restrict__ means,
                            const float* __restrict__ scales,
                            const float* __restrict__ thetas,
                            const float* __restrict__ opacities) {
    int i = blockIdx.x * blockDim.x + threadIdx.x;
    if (i >= NG) return;

    float mx = tanhf(means[2 * i + 0]);
    float my = tanhf(means[2 * i + 1]);
    float s0 = expf(scales[2 * i + 0]);
    float s1 = expf(scales[2 * i + 1]);
    float th = (2.0f * 3.14159265358979323846f) / (1.0f + expf(-thetas[i]));
    float op = 1.0f / (1.0f + expf(-opacities[i]));

    float si, c;
    sincosf(th, &si, &c);
    float s02 = s0 * s0, s12 = s1 * s1;
    const float J = 1e-6f;
    float a = c * c * s02 + si * si * s12 + J;   // Sigma_00
    float b = c * si * (s02 - s12);              // Sigma_01
    float d = si * si * s02 + c * c * s12 + J;   // Sigma_11
    float det = a * d - b * b;
    float inv = 1.0f / det;

    g_pos[i] = make_float4(mx, my, sqrtf(QMAX * a), sqrtf(QMAX * d));
    g_cov[i] = make_float4(d * inv, -b * inv, a * inv, op);
}

__global__ void __launch_bounds__(256) render_kernel() {
    __shared__ float4 sp[CHUNK];       // mx, my, ia, ib   (4KB)
    __shared__ float2 sc[CHUNK];       // id, op           (2KB)
    __shared__ int warp_cnt[8];
    __shared__ int warp_off[8];
    __shared__ int s_total;

    const int tid  = threadIdx.y * 16 + threadIdx.x;
    const int warp = tid >> 5;
    const int lane = tid & 31;
    const float h = 2.0f / 255.0f;

    // Tile rect (center + half extent in [-1,1] coords)
    const float cx   = -1.0f + ((float)(blockIdx.x * 16) + 7.5f) * h;
    const float cy   = -1.0f + ((float)(blockIdx.y * 16) + 7.5f) * h;
    const float half = 7.5f * h;

    // ---- Stage + stable compaction of this chunk's gaussians vs tile bbox ----
    const int gi = blockIdx.z * CHUNK + tid;
    float4 pos = g_pos[gi];
    float4 cov = g_cov[gi];
    bool pass = (fabsf(pos.x - cx) < pos.z + half) &&
                (fabsf(pos.y - cy) < pos.w + half);

    unsigned bal = __ballot_sync(0xffffffffu, pass);
    int pre = __popc(bal & ((1u << lane) - 1u));
    if (lane == 0) warp_cnt[warp] = __popc(bal);
    __syncthreads();
    if (tid == 0) {
        int s = 0;
        #pragma unroll
        for (int w = 0; w < 8; ++w) { warp_off[w] = s; s += warp_cnt[w]; }
        s_total = s;
    }
    __syncthreads();
    if (pass) {
        int slot = warp_off[warp] + pre;
        sp[slot] = make_float4(pos.x, pos.y, cov.x, cov.y);
        sc[slot] = make_float2(cov.z, cov.w);
    }
    __syncthreads();
    const int cnt = s_total;

    // ---- Per-pixel composite over compacted list (order preserved) ----
    const int px = blockIdx.x * 16 + threadIdx.x;
    const int py = blockIdx.y * 16 + threadIdx.y;
    const float x = -1.0f + (float)px * h;
    const float y = -1.0f + (float)py * h;

    float acc = 0.0f;
    float T = 1.0f;

    #pragma unroll 2
    for (int i = 0; i < cnt; ++i) {
        float4 p  = sp[i];
        float2 c2 = sc[i];
        float dx = x - p.x;
        float dy = y - p.y;
        float u = p.z * dx + p.w * dy;
        float v = p.w * dx + c2.x * dy;
        float q = u * dx + v * dy;          // Mahalanobis dist^2
        if (q < QMAX) {
            float alpha = c2.y * __expf(-0.5f * q);
            acc += alpha * T;
            T   -= alpha * T;               // T *= (1 - alpha)
        }
    }

    g_part[blockIdx.z * NPIX + py * IMG_W + px] = make_float2(acc, T);
}

__global__ void __launch_bounds__(256) combine_kernel(float* __restrict__ out) {
    int p = blockIdx.x * 256 + threadIdx.x;
    float2 r0 = g_part[0 * NPIX + p];
    float2 r1 = g_part[1 * NPIX + p];
    float2 r2 = g_part[2 * NPIX + p];
    float2 r3 = g_part[3 * NPIX + p];
    // Sequential composition: acc = a0 + T0*(a1 + T1*(a2 + T2*a3))
    float acc = r0.x + r0.y * (r1.x + r1.y * (r2.x + r2.y * r3.x));
    int o = p * 3;
    out[o + 0] = acc;
    out[o + 1] = acc;
    out[o + 2] = acc;   // BG = 0, all channels equal
}

extern "C" void kernel_launch(void* const* d_in, const int* in_sizes, int n_in,
                              void* d_out, int out_size) {
    const float* means     = (const float*)d_in[0];
    const float* scales    = (const float*)d_in[1];
    const float* thetas    = (const float*)d_in[2];
    const float* opacities = (const float*)d_in[3];
    float* out = (float*)d_out;

    prep_kernel<<<4, 256>>>(means, scales, thetas, opacities);
    render_kernel<<<dim3(IMG_W / 16, IMG_H / 16, NCHUNK), dim3(16, 16)>>>();
    combine_kernel<<<NPIX / 256, 256>>>(out);
}

// round 4
// speedup vs baseline: 2.9944x; 1.1045x over previous
#include <cuda_runtime.h>
#include <cuda_bf16.h>

#define NG      1024
#define NCHUNK  4
#define CHUNK   (NG / NCHUNK)          // 256
#define IMG_W   256
#define IMG_H   256
#define NPIX    (IMG_W * IMG_H)
#define QMAX    18.0f                  // bbox truncation: per-gaussian alpha < op*e^-9

// Per-pixel partial composites, interleaved [pixel][chunk]: (acc,T) pairs.
// pixel p, chunk z at g_part[p*NCHUNK + z] (float2) -> combine reads 2x float4.
__device__ float2 g_part[NPIX * NCHUNK];

__device__ __forceinline__ float fast_sigmoid(float x) {
    return 1.0f / (1.0f + __expf(-x));
}

__global__ void __launch_bounds__(256) render_kernel(
        const float* __restrict__ means,
        const float* __restrict__ scales,
        const float* __restrict__ thetas,
        const float* __restrict__ opacities) {
    __shared__ float4 sp[CHUNK];       // mx, my, ia2, ib2   (pre-scaled by -0.5*log2e)
    __shared__ float2 sc[CHUNK];       // id2, op
    __shared__ int warp_cnt[8];
    __shared__ int warp_off[8];
    __shared__ int s_total;

    const int tid  = threadIdx.y * 16 + threadIdx.x;
    const int warp = tid >> 5;
    const int lane = tid & 31;
    const float h = 2.0f / 255.0f;

    // ---- In-CTA prep of this chunk's gaussian (one per thread) ----
    const int gi = blockIdx.z * CHUNK + tid;
    float mx = means[2 * gi + 0];
    float my = means[2 * gi + 1];
    {   // tanh via exp: tanh(x) = 1 - 2/(e^{2x}+1)
        float ex = __expf(2.0f * mx);
        mx = 1.0f - 2.0f / (ex + 1.0f);
        float ey = __expf(2.0f * my);
        my = 1.0f - 2.0f / (ey + 1.0f);
    }
    float s0 = __expf(scales[2 * gi + 0]);
    float s1 = __expf(scales[2 * gi + 1]);
    float th = fast_sigmoid(thetas[gi]) * 6.283185307179586f;
    float op = fast_sigmoid(opacities[gi]);

    float si, c;
    __sincosf(th, &si, &c);
    float s02 = s0 * s0, s12 = s1 * s1;
    const float J = 1e-6f;
    float a = c * c * s02 + si * si * s12 + J;   // Sigma_00
    float b = c * si * (s02 - s12);              // Sigma_01
    float d = si * si * s02 + c * c * s12 + J;   // Sigma_11
    float inv = 1.0f / (a * d - b * b);
    const float NEG_HALF_LOG2E = -0.7213475204444817f;   // -0.5 * log2(e)
    float ia2 =  d * inv * NEG_HALF_LOG2E;
    float ib2 = -b * inv * NEG_HALF_LOG2E;
    float id2 =  a * inv * NEG_HALF_LOG2E;
    float rx = sqrtf(QMAX * a);
    float ry = sqrtf(QMAX * d);

    // ---- Tile bbox test + stable compaction into smem ----
    const float cx   = -1.0f + ((float)(blockIdx.x * 16) + 7.5f) * h;
    const float cy   = -1.0f + ((float)(blockIdx.y * 16) + 7.5f) * h;
    const float half = 7.5f * h;
    bool pass = (fabsf(mx - cx) < rx + half) && (fabsf(my - cy) < ry + half);

    unsigned bal = __ballot_sync(0xffffffffu, pass);
    int pre = __popc(bal & ((1u << lane) - 1u));
    if (lane == 0) warp_cnt[warp] = __popc(bal);
    __syncthreads();
    if (tid == 0) {
        int s = 0;
        #pragma unroll
        for (int w = 0; w < 8; ++w) { warp_off[w] = s; s += warp_cnt[w]; }
        s_total = s;
    }
    __syncthreads();
    if (pass) {
        int slot = warp_off[warp] + pre;
        sp[slot] = make_float4(mx, my, ia2, ib2);
        sc[slot] = make_float2(id2, op);
    }
    __syncthreads();
    const int cnt = s_total;

    // ---- Per-pixel branchless composite over compacted list (order kept) ----
    const int px = blockIdx.x * 16 + threadIdx.x;
    const int py = blockIdx.y * 16 + threadIdx.y;
    const float x = -1.0f + (float)px * h;
    const float y = -1.0f + (float)py * h;

    float acc = 0.0f;
    float T = 1.0f;

    #pragma unroll 4
    for (int i = 0; i < cnt; ++i) {
        float4 p  = sp[i];
        float2 c2 = sc[i];
        float dx = x - p.x;
        float dy = y - p.y;
        float u = fmaf(p.z, dx, p.w * dy);          // -0.5*log2e * (ia*dx + ib*dy)
        float v = fmaf(p.w, dx, c2.x * dy);
        float qh = fmaf(u, dx, v * dy);             // -0.5*log2e * q
        float alpha = c2.y * exp2f(qh);             // single MUFU.EX2
        float aT = alpha * T;
        acc += aT;
        T   -= aT;
    }

    g_part[(py * IMG_W + px) * NCHUNK + blockIdx.z] = make_float2(acc, T);
}

__global__ void __launch_bounds__(256) combine_kernel(float* __restrict__ out) {
    int p = blockIdx.x * 256 + threadIdx.x;
    const float4* g4 = (const float4*)g_part;
    float4 u0 = g4[p * 2 + 0];    // (acc0,T0,acc1,T1)
    float4 u1 = g4[p * 2 + 1];    // (acc2,T2,acc3,T3)
    // acc = a0 + T0*(a1 + T1*(a2 + T2*a3))
    float acc = fmaf(u0.y, fmaf(u0.w, fmaf(u1.y, u1.z, u1.x), u0.z), u0.x);
    int o = p * 3;
    out[o + 0] = acc;
    out[o + 1] = acc;
    out[o + 2] = acc;   // BG = 0, all channels equal
}

extern "C" void kernel_launch(void* const* d_in, const int* in_sizes, int n_in,
                              void* d_out, int out_size) {
    const float* means     = (const float*)d_in[0];
    const float* scales    = (const float*)d_in[1];
    const float* thetas    = (const float*)d_in[2];
    const float* opacities = (const float*)d_in[3];
    float* out = (float*)d_out;

    render_kernel<<<dim3(IMG_W / 16, IMG_H / 16, NCHUNK), dim3(16, 16)>>>(
        means, scales, thetas, opacities);
    combine_kernel<<<NPIX / 256, 256>>>(out);
}